// round 14
// baseline (speedup 1.0000x reference)
#include <cuda_runtime.h>
#include <cuda_fp16.h>
#include <math.h>
#include <cstdint>

#define Bsz 4
#define Ssz 2048
#define Csz 1024
#define Hn  16
#define Dh  64
#define Msz (Bsz*Ssz)   // 8192

// Scratch (all fp16)
__device__ __half g_a[3][(size_t)Msz*Csz];        // activation planes A
__device__ __half g_b[3][(size_t)Msz*Csz];        // activation planes B
__device__ __half g_o[(size_t)Msz*Csz];           // attention output
__device__ __half g_vb[(size_t)Msz*Csz];          // V^T per (b,h): [d][s]
__device__ __half g_w[3][(size_t)Csz*Csz];        // weights [N,K]

// ---------------------------------------------------------------------------
// PTX helpers
// ---------------------------------------------------------------------------
__device__ __forceinline__ uint32_t smem_u32(const void* p) {
    uint32_t a;
    asm("{ .reg .u64 t; cvta.to.shared.u64 t, %1; cvt.u32.u64 %0, t; }" : "=r"(a) : "l"(p));
    return a;
}
__device__ __forceinline__ void cp16(uint32_t saddr, const void* g) {
    asm volatile("cp.async.cg.shared.global [%0], [%1], 16;" :: "r"(saddr), "l"(g));
}
__device__ __forceinline__ void cp4(uint32_t saddr, const void* g) {
    asm volatile("cp.async.ca.shared.global [%0], [%1], 4;" :: "r"(saddr), "l"(g));
}
#define CP_COMMIT() asm volatile("cp.async.commit_group;" ::: "memory")
#define CP_WAIT1()  asm volatile("cp.async.wait_group 1;" ::: "memory")
#define CP_WAIT0()  asm volatile("cp.async.wait_group 0;" ::: "memory")

#define LDSM4(r, addr)                                                          \
    asm volatile("ldmatrix.sync.aligned.m8n8.x4.shared.b16 {%0,%1,%2,%3}, [%4];" \
        : "=r"((r)[0]), "=r"((r)[1]), "=r"((r)[2]), "=r"((r)[3]) : "r"(addr))
#define LDSM2(r, addr)                                                          \
    asm volatile("ldmatrix.sync.aligned.m8n8.x2.shared.b16 {%0,%1}, [%2];"      \
        : "=r"((r)[0]), "=r"((r)[1]) : "r"(addr))

#define MMA16816(d, a, b)                                                       \
    asm volatile("mma.sync.aligned.m16n8k16.row.col.f32.f16.f16.f32 "           \
        "{%0,%1,%2,%3}, {%4,%5,%6,%7}, {%8,%9}, {%0,%1,%2,%3};"                 \
        : "+f"((d)[0]), "+f"((d)[1]), "+f"((d)[2]), "+f"((d)[3])                \
        : "r"((a)[0]), "r"((a)[1]), "r"((a)[2]), "r"((a)[3]),                   \
          "r"((b)[0]), "r"((b)[1]))

__device__ __forceinline__ uint32_t pack_f16(float lo, float hi) {
    uint32_t r;
    asm("cvt.rn.f16x2.f32 %0, %1, %2;" : "=r"(r) : "f"(hi), "f"(lo));
    return r;
}

// Swizzled smem offset for a [rows x 32] f16 tile (64B rows): granule g 0..3
__device__ __forceinline__ uint32_t tswz(int r, int g) {
    return (uint32_t)(r * 64 + ((g ^ ((r >> 1) & 3)) & 3) * 16);
}
// Swizzled offset for 128B rows (64 f16): granule g 0..7
__device__ __forceinline__ uint32_t tswz128(int r, int g) {
    return (uint32_t)(r * 128 + ((g ^ (r & 7)) & 7) * 16);
}

// ---------------------------------------------------------------------------
// Convert fp32 -> fp16 (plain)
// ---------------------------------------------------------------------------
__global__ void cvt_f16_k(const float* __restrict__ in, __half* __restrict__ out)
{
    const size_t i4 = (size_t)blockIdx.x * blockDim.x + threadIdx.x;
    float4 v = *(const float4*)(in + i4 * 4);
    *(__half2*)(out + i4*4)     = __floats2half2_rn(v.x, v.y);
    *(__half2*)(out + i4*4 + 2) = __floats2half2_rn(v.z, v.w);
}

// Batched plain convert of 3 weight matrices [N,K] fp32 -> fp16
__global__ void cvt3_k(const float* __restrict__ p0, const float* __restrict__ p1,
                       const float* __restrict__ p2, __half* __restrict__ out)
{
    const int z = blockIdx.y;
    const float* in = (z == 0) ? p0 : ((z == 1) ? p1 : p2);
    __half* o = out + (size_t)z * Csz * Csz;
    const size_t i4 = (size_t)blockIdx.x * blockDim.x + threadIdx.x;
    float4 v = *(const float4*)(in + i4 * 4);
    *(__half2*)(o + i4*4)     = __floats2half2_rn(v.x, v.y);
    *(__half2*)(o + i4*4 + 2) = __floats2half2_rn(v.z, v.w);
}

// ---------------------------------------------------------------------------
// Batched transpose+convert: W[K,N] fp32 -> [N,K] fp16 (z = blockIdx.z)
// ---------------------------------------------------------------------------
__global__ void cvt_trans3_k(const float* __restrict__ p0, const float* __restrict__ p1,
                             const float* __restrict__ p2, __half* __restrict__ out,
                             int K, int N)
{
    __shared__ float t[32][33];
    const int z = blockIdx.z;
    const float* W = (z == 0) ? p0 : ((z == 1) ? p1 : p2);
    __half* o = out + (size_t)z * K * N;
    const int k0 = blockIdx.y * 32, n0 = blockIdx.x * 32;
    const int tx = threadIdx.x, ty = threadIdx.y;
#pragma unroll
    for (int r = 0; r < 4; r++)
        t[ty + r*8][tx] = W[(size_t)(k0 + ty + r*8) * N + n0 + tx];
    __syncthreads();
#pragma unroll
    for (int r = 0; r < 4; r++) {
        const int n = n0 + ty + r*8, k = k0 + tx;
        o[(size_t)n * K + k] = __float2half_rn(t[tx][ty + r*8]);
    }
}

// ---------------------------------------------------------------------------
// V transpose (fp16 in): in [B,S,C] -> vt[(bh*64 + d)*Ssz + s]
// ---------------------------------------------------------------------------
__global__ void vtrans_k(const __half* __restrict__ in, __half* __restrict__ vt)
{
    __shared__ float t[32][33];
    const int z = blockIdx.y;
    const int dblk = z & 1, bh = z >> 1;
    const int b = bh >> 4, h = bh & 15;
    const int s0 = blockIdx.x * 32;
    const int tx = threadIdx.x, ty = threadIdx.y;
#pragma unroll
    for (int r = 0; r < 4; r++)
        t[ty + r*8][tx] = __half2float(
            in[(size_t)(b*Ssz + s0 + ty + r*8) * Csz + h*Dh + dblk*32 + tx]);
    __syncthreads();
#pragma unroll
    for (int r = 0; r < 4; r++) {
        const int d = dblk*32 + ty + r*8;
        vt[((size_t)bh * Dh + d) * Ssz + s0 + tx] = __float2half_rn(t[tx][ty + r*8]);
    }
}

// ---------------------------------------------------------------------------
// Plain fp16 GEMM on mma.sync, batched over blockIdx.z.
// C[M,N] = act(A @ B^T + bias); OUTH selects fp16 vs fp32 output.
// 128x128 tile, BK=32, 256 threads, 2-stage cp.async pipeline.
// ---------------------------------------------------------------------------
#define G_STG 16384
__device__ __forceinline__ void stage_load(
    const __half* __restrict__ A, const __half* __restrict__ B,
    int K, int m0, int n0, int k0, uint32_t sb)
{
    const int t = threadIdx.x;
    const int r = t >> 1;
    const int g0 = (t & 1) * 2;
    const size_t arow = (size_t)(m0 + r) * K + k0;
    const size_t brow = (size_t)(n0 + r) * K + k0;
#pragma unroll
    for (int gg = 0; gg < 2; gg++) {
        const int g = g0 + gg;
        const uint32_t so = tswz(r, g);
        cp16(sb + so,        A + arow + g*8);
        cp16(sb + 8192 + so, B + brow + g*8);
    }
}

template<int ACT, int OUTH>
__global__ __launch_bounds__(256, 1) void gemm_f16_k(
    const __half* __restrict__ A_, const __half* __restrict__ B_,
    const float* __restrict__ bias0, const float* __restrict__ bias1,
    const float* __restrict__ bias2,
    void* __restrict__ C_,
    int M, int N, int K, size_t strideA, size_t strideB, size_t strideC)
{
    extern __shared__ char sm_[];
    const uint32_t sbase = smem_u32(sm_);
    const int tid  = threadIdx.x;
    const int lane = tid & 31;
    const int warp = tid >> 5;
    const int wm = warp >> 2;
    const int wn = warp & 3;
    const int m0 = blockIdx.y * 128, n0 = blockIdx.x * 128;
    const int z  = blockIdx.z;

    const __half* A = A_ + (size_t)z * strideA;
    const __half* B = B_ + (size_t)z * strideB;
    const float* bias = (z == 0) ? bias0 : ((z == 1) ? bias1 : bias2);

    float acc[4][4][4];
#pragma unroll
    for (int i = 0; i < 4; i++)
#pragma unroll
        for (int j = 0; j < 4; j++)
#pragma unroll
            for (int c = 0; c < 4; c++) acc[i][j][c] = 0.f;

    const int NIT = K >> 5;

    stage_load(A, B, K, m0, n0, 0, sbase);
    CP_COMMIT();

    for (int it = 0; it < NIT; it++) {
        if (it + 1 < NIT) {
            stage_load(A, B, K, m0, n0, (it+1) << 5,
                       sbase + ((it+1) & 1) * G_STG);
            CP_COMMIT();
            CP_WAIT1();
        } else {
            CP_WAIT0();
        }
        __syncthreads();

        const uint32_t sb = sbase + (it & 1) * G_STG;
        const int lr  = lane & 15;
        const int hf  = lane >> 4;
        const int lnb = lane & 7;
        const int hfb = (lane >> 3) & 1;

#pragma unroll
        for (int kk = 0; kk < 2; kk++) {
            uint32_t ah[4][4], bfr[4][2];
#pragma unroll
            for (int mt = 0; mt < 4; mt++) {
                const int r = wm*64 + mt*16 + lr;
                LDSM4(ah[mt], sb + tswz(r, kk*2 + hf));
            }
#pragma unroll
            for (int nt = 0; nt < 4; nt++) {
                const int rn = wn*32 + nt*8 + lnb;
                LDSM2(bfr[nt], sb + 8192 + tswz(rn, kk*2 + hfb));
            }
#pragma unroll
            for (int mt = 0; mt < 4; mt++)
#pragma unroll
                for (int nt = 0; nt < 4; nt++)
                    MMA16816(acc[mt][nt], ah[mt], bfr[nt]);
        }
        __syncthreads();
    }

    const int gid = lane >> 2;
    const int tg  = lane & 3;
    float*  Cf = (float*)C_  + (size_t)z * strideC;
    __half* Ch = (__half*)C_ + (size_t)z * strideC;
#pragma unroll
    for (int mt = 0; mt < 4; mt++) {
#pragma unroll
        for (int nt = 0; nt < 4; nt++) {
            const int ncol = n0 + wn*32 + nt*8 + tg*2;
            const float b0 = __ldg(&bias[ncol]);
            const float b1 = __ldg(&bias[ncol + 1]);
#pragma unroll
            for (int h = 0; h < 2; h++) {
                const int row = m0 + wm*64 + mt*16 + gid + h*8;
                float v0 = acc[mt][nt][h*2 + 0] + b0;
                float v1 = acc[mt][nt][h*2 + 1] + b1;
                if (ACT) {
                    v0 = v0 / (1.f + __expf(-v0));
                    v1 = v1 / (1.f + __expf(-v1));
                }
                if (OUTH) {
                    *(__half2*)(Ch + (size_t)row * N + ncol) = __floats2half2_rn(v0, v1);
                } else {
                    *(float2*)(Cf + (size_t)row * N + ncol) = make_float2(v0, v1);
                }
            }
        }
    }
}

// ---------------------------------------------------------------------------
// Fused depthwise conv k=3, fp16 in -> fp16 out. Batched over z. 8-wide.
// ---------------------------------------------------------------------------
__global__ void dwconv_f16_k(
    const __half* __restrict__ in_,
    const float* __restrict__ dw0, const float* __restrict__ dw1, const float* __restrict__ dw2,
    const float* __restrict__ db0, const float* __restrict__ db1, const float* __restrict__ db2,
    __half* __restrict__ out_)
{
    const int z = blockIdx.y;
    const __half* in = in_ + (size_t)z * Msz * Csz;
    const float* dw  = (z == 0) ? dw0 : ((z == 1) ? dw1 : dw2);
    const float* dwb = (z == 0) ? db0 : ((z == 1) ? db1 : db2);
    __half* out = out_ + (size_t)z * Msz * Csz;

    const int idx = blockIdx.x * blockDim.x + threadIdx.x;   // over Msz*Csz/8
    const int c8 = (idx & (Csz/8 - 1)) * 8;
    const int m  = idx >> 7;
    const int s  = m & (Ssz - 1);

    uint4 zz = make_uint4(0,0,0,0);
    uint4 x0 = (s > 0)       ? *(const uint4*)(in + (size_t)(m-1)*Csz + c8) : zz;
    uint4 x1 =                 *(const uint4*)(in + (size_t)m*Csz + c8);
    uint4 x2 = (s < Ssz - 1) ? *(const uint4*)(in + (size_t)(m+1)*Csz + c8) : zz;

    const __half* h0 = (const __half*)&x0;
    const __half* h1 = (const __half*)&x1;
    const __half* h2 = (const __half*)&x2;
    __half res[8];
#pragma unroll
    for (int t = 0; t < 8; t++) {
        const int c = c8 + t;
        const float v = dwb[c] + dw[c*3+0]*__half2float(h0[t])
                               + dw[c*3+1]*__half2float(h1[t])
                               + dw[c*3+2]*__half2float(h2[t]);
        res[t] = __float2half_rn(v);
    }
    *(uint4*)(out + (size_t)m*Csz + c8) = *(uint4*)res;
}

// ---------------------------------------------------------------------------
// L2 normalize over C=1024, fp16 in -> fp16 out.
// ---------------------------------------------------------------------------
__global__ void l2norm_f16_k(const __half* __restrict__ src, __half* __restrict__ dst)
{
    __shared__ float red[8];
    const __half* p = src + (size_t)blockIdx.x * Csz;
    __half2 a = *(const __half2*)(p + threadIdx.x*4);
    __half2 b = *(const __half2*)(p + threadIdx.x*4 + 2);
    float2 fa = __half22float2(a), fb = __half22float2(b);
    float ss = fa.x*fa.x + fa.y*fa.y + fb.x*fb.x + fb.y*fb.y;
#pragma unroll
    for (int off = 16; off; off >>= 1) ss += __shfl_xor_sync(0xffffffffu, ss, off);
    if ((threadIdx.x & 31) == 0) red[threadIdx.x >> 5] = ss;
    __syncthreads();
    if (threadIdx.x == 0) {
        float t = 0.f;
#pragma unroll
        for (int i = 0; i < 8; i++) t += red[i];
        red[0] = t;
    }
    __syncthreads();
    const float inv = 1.0f / fmaxf(sqrtf(red[0]), 1e-12f);
    __half* d = dst + (size_t)blockIdx.x * Csz + threadIdx.x*4;
    *(__half2*)(d)     = __floats2half2_rn(fa.x*inv, fa.y*inv);
    *(__half2*)(d + 2) = __floats2half2_rn(fb.x*inv, fb.y*inv);
}

// ---------------------------------------------------------------------------
// Flash attention on mma.sync (fp16 in, fp32 accum). Output plain fp16.
// ---------------------------------------------------------------------------
#define ATT_STG 16640
__device__ __forceinline__ void attn_stage(
    const __half* __restrict__ kb, const __half* __restrict__ vt,
    const int* __restrict__ mask, size_t qkbase, size_t vbase, int b,
    int chunk, uint32_t st)
{
    const int tid = threadIdx.x;
#pragma unroll
    for (int i = 0; i < 2; i++) {
        const int idx = tid + i*256;
        const int r = idx >> 3, g = idx & 7;
        const uint32_t so = tswz128(r, g);
        cp16(st + so,        kb + qkbase + (size_t)(chunk*64 + r) * Csz + g*8);
        cp16(st + 8192 + so, vt + vbase + (size_t)r * Ssz + chunk*64 + g*8);
    }
    if (tid < 64)
        cp4(st + 16384 + tid*4, mask + (size_t)b * Ssz + chunk*64 + tid);
}

__global__ __launch_bounds__(256, 1) void attn2_k(
    const __half* __restrict__ qb, const __half* __restrict__ kb,
    const __half* __restrict__ vt, const int* __restrict__ mask,
    __half* __restrict__ og)
{
    extern __shared__ char sm_[];
    const uint32_t sbase = smem_u32(sm_);
    const int tid = threadIdx.x, lane = tid & 31, warp = tid >> 5;
    const int q0 = blockIdx.x * 128;
    const int bh = blockIdx.y;
    const int b = bh >> 4, h = bh & 15;

    const size_t qkbase = ((size_t)b * Ssz) * Csz + h * Dh;
    const size_t vbase  = (size_t)bh * Dh * Ssz;

#pragma unroll
    for (int i = 0; i < 4; i++) {
        const int idx = tid + i*256;
        const int r = idx >> 3, g = idx & 7;
        cp16(sbase + tswz128(r, g), qb + qkbase + (size_t)(q0 + r) * Csz + g*8);
    }
    CP_COMMIT();

    const uint32_t kvb = sbase + 16384;
    attn_stage(kb, vt, mask, qkbase, vbase, b, 0, kvb);
    CP_COMMIT();

    float oacc[8][4];
#pragma unroll
    for (int nt = 0; nt < 8; nt++)
#pragma unroll
        for (int c = 0; c < 4; c++) oacc[nt][c] = 0.f;
    float m0 = -1e30f, m1 = -1e30f, l0 = 0.f, l1 = 0.f;
    uint32_t aq[4][4];

    const int cb = (lane & 3) * 2;

    for (int it = 0; it < Ssz/64; it++) {
        if (it + 1 < Ssz/64) {
            attn_stage(kb, vt, mask, qkbase, vbase, b, it+1, kvb + ((it+1)&1)*ATT_STG);
            CP_COMMIT();
            CP_WAIT1();
        } else {
            CP_WAIT0();
        }
        __syncthreads();

        if (it == 0) {
#pragma unroll
            for (int ks = 0; ks < 4; ks++) {
                const int r = warp*16 + (lane & 15);
                const int g = ks*2 + (lane >> 4);
                LDSM4(aq[ks], sbase + tswz128(r, g));
            }
        }

        const uint32_t st = kvb + (it & 1) * ATT_STG;
        const int* Ms = (const int*)(sm_ + 16384 + (it & 1) * ATT_STG + 16384);

        float sacc[8][4];
#pragma unroll
        for (int nt = 0; nt < 8; nt++)
#pragma unroll
            for (int c = 0; c < 4; c++) sacc[nt][c] = 0.f;

#pragma unroll
        for (int ks = 0; ks < 4; ks++) {
#pragma unroll
            for (int nt = 0; nt < 8; nt++) {
                uint32_t kf[2];
                const int r = nt*8 + (lane & 7);
                const int g = ks*2 + ((lane >> 3) & 1);
                LDSM2(kf, st + tswz128(r, g));
                MMA16816(sacc[nt], aq[ks], kf);
            }
        }

        float mx0 = -1e30f, mx1 = -1e30f;
#pragma unroll
        for (int nt = 0; nt < 8; nt++) {
            const int c = nt*8 + cb;
            const bool k0m = Ms[c] != 0, k1m = Ms[c+1] != 0;
            sacc[nt][0] = k0m ? sacc[nt][0]*0.125f : -1e30f;
            sacc[nt][1] = k1m ? sacc[nt][1]*0.125f : -1e30f;
            sacc[nt][2] = k0m ? sacc[nt][2]*0.125f : -1e30f;
            sacc[nt][3] = k1m ? sacc[nt][3]*0.125f : -1e30f;
            mx0 = fmaxf(mx0, fmaxf(sacc[nt][0], sacc[nt][1]));
            mx1 = fmaxf(mx1, fmaxf(sacc[nt][2], sacc[nt][3]));
        }
        mx0 = fmaxf(mx0, __shfl_xor_sync(0xffffffffu, mx0, 1));
        mx0 = fmaxf(mx0, __shfl_xor_sync(0xffffffffu, mx0, 2));
        mx1 = fmaxf(mx1, __shfl_xor_sync(0xffffffffu, mx1, 1));
        mx1 = fmaxf(mx1, __shfl_xor_sync(0xffffffffu, mx1, 2));
        const float mn0 = fmaxf(m0, mx0), mn1 = fmaxf(m1, mx1);
        const float c0 = __expf(m0 - mn0), c1 = __expf(m1 - mn1);
        m0 = mn0; m1 = mn1;
        float rs0 = 0.f, rs1 = 0.f;
#pragma unroll
        for (int nt = 0; nt < 8; nt++) {
            sacc[nt][0] = __expf(sacc[nt][0] - mn0);
            sacc[nt][1] = __expf(sacc[nt][1] - mn0);
            sacc[nt][2] = __expf(sacc[nt][2] - mn1);
            sacc[nt][3] = __expf(sacc[nt][3] - mn1);
            rs0 += sacc[nt][0] + sacc[nt][1];
            rs1 += sacc[nt][2] + sacc[nt][3];
        }
        rs0 += __shfl_xor_sync(0xffffffffu, rs0, 1);
        rs0 += __shfl_xor_sync(0xffffffffu, rs0, 2);
        rs1 += __shfl_xor_sync(0xffffffffu, rs1, 1);
        rs1 += __shfl_xor_sync(0xffffffffu, rs1, 2);
        l0 = l0*c0 + rs0;
        l1 = l1*c1 + rs1;
#pragma unroll
        for (int nt = 0; nt < 8; nt++) {
            oacc[nt][0] *= c0; oacc[nt][1] *= c0;
            oacc[nt][2] *= c1; oacc[nt][3] *= c1;
        }

#pragma unroll
        for (int ks = 0; ks < 4; ks++) {
            uint32_t pa[4];
            pa[0] = pack_f16(sacc[2*ks][0],   sacc[2*ks][1]);
            pa[1] = pack_f16(sacc[2*ks][2],   sacc[2*ks][3]);
            pa[2] = pack_f16(sacc[2*ks+1][0], sacc[2*ks+1][1]);
            pa[3] = pack_f16(sacc[2*ks+1][2], sacc[2*ks+1][3]);
#pragma unroll
            for (int nt = 0; nt < 8; nt++) {
                uint32_t vf[2];
                const int r = nt*8 + (lane & 7);
                const int g = ks*2 + ((lane >> 3) & 1);
                LDSM2(vf, st + 8192 + tswz128(r, g));
                MMA16816(oacc[nt], pa, vf);
            }
        }
        __syncthreads();
    }

    const float inv0 = 1.f / l0, inv1 = 1.f / l1;
    const int r0 = q0 + warp*16 + (lane >> 2);
#pragma unroll
    for (int nt = 0; nt < 8; nt++) {
        const int c = h*Dh + nt*8 + cb;
        *(__half2*)(og + ((size_t)b*Ssz + r0) * Csz + c) =
            __floats2half2_rn(oacc[nt][0]*inv0, oacc[nt][1]*inv0);
        *(__half2*)(og + ((size_t)b*Ssz + r0 + 8) * Csz + c) =
            __floats2half2_rn(oacc[nt][2]*inv1, oacc[nt][3]*inv1);
    }
}

// ---------------------------------------------------------------------------
extern "C" void kernel_launch(void* const* d_in, const int* in_sizes, int n_in,
                              void* d_out, int out_size)
{
    const float* x    = (const float*)d_in[0];
    const int*   mask = (const int*)  d_in[1];
    const float* W[3]   = {(const float*)d_in[2],  (const float*)d_in[8],  (const float*)d_in[14]};
    const float* Bi[3]  = {(const float*)d_in[3],  (const float*)d_in[9],  (const float*)d_in[15]};
    const float* DW[3]  = {(const float*)d_in[4],  (const float*)d_in[10], (const float*)d_in[16]};
    const float* DWB[3] = {(const float*)d_in[5],  (const float*)d_in[11], (const float*)d_in[17]};
    const float* PW[3]  = {(const float*)d_in[6],  (const float*)d_in[12], (const float*)d_in[18]};
    const float* PWB[3] = {(const float*)d_in[7],  (const float*)d_in[13], (const float*)d_in[19]};
    const float* wo = (const float*)d_in[20];
    const float* bo = (const float*)d_in[21];
    float* out = (float*)d_out;

    __half *ga, *gb, *go, *vb, *gw;
    cudaGetSymbolAddress((void**)&ga, g_a);
    cudaGetSymbolAddress((void**)&gb, g_b);
    cudaGetSymbolAddress((void**)&go, g_o);
    cudaGetSymbolAddress((void**)&vb, g_vb);
    cudaGetSymbolAddress((void**)&gw, g_w);
    const size_t PL = (size_t)Msz * Csz;
    const size_t WL = (size_t)Csz * Csz;

    const int GEMM_SMEM = 2 * G_STG;            // 32768
    const int ATT_SMEM  = 16384 + 2*ATT_STG;    // 49664
    cudaFuncSetAttribute(gemm_f16_k<0,0>, cudaFuncAttributeMaxDynamicSharedMemorySize, GEMM_SMEM);
    cudaFuncSetAttribute(gemm_f16_k<0,1>, cudaFuncAttributeMaxDynamicSharedMemorySize, GEMM_SMEM);
    cudaFuncSetAttribute(gemm_f16_k<1,1>, cudaFuncAttributeMaxDynamicSharedMemorySize, GEMM_SMEM);
    cudaFuncSetAttribute(attn2_k, cudaFuncAttributeMaxDynamicSharedMemorySize, ATT_SMEM);

    const dim3 ggemm1(Csz/128, Msz/128, 1);
    const dim3 ggemm3(Csz/128, Msz/128, 3);
    const dim3 gtr3(Csz/32, Csz/32, 3), btr(32, 8);

    // 1) x -> fp16 (ga0)
    cvt_f16_k<<<(Msz*Csz/4)/256, 256>>>(x, ga);

    // 2) QKV weights -> [N,K] fp16 (batched)
    cvt_trans3_k<<<gtr3, btr>>>(W[0], W[1], W[2], gw, Csz, Csz);

    // 3) batched QKV GEMM: q/k/v = silu(x @ W + b) -> gb[z] (fp16)
    gemm_f16_k<1,1><<<ggemm3, 256, GEMM_SMEM>>>(
        ga, gw, Bi[0], Bi[1], Bi[2], gb,
        Msz, Csz, Csz, 0, WL, PL);

    // 4) depthwise conv fp16->fp16: gb[z] -> ga[z]
    dwconv_f16_k<<<dim3((Msz*Csz/8)/256, 3), 256>>>(
        gb, DW[0], DW[1], DW[2], DWB[0], DWB[1], DWB[2], ga);

    // 5) pointwise weights (already [N,K]) -> fp16 (batched)
    cvt3_k<<<dim3((Csz*Csz/4)/256, 3), 256>>>(PW[0], PW[1], PW[2], gw);

    // 6) batched pointwise GEMM -> gb[z] (fp16)
    gemm_f16_k<0,1><<<ggemm3, 256, GEMM_SMEM>>>(
        ga, gw, PWB[0], PWB[1], PWB[2], gb,
        Msz, Csz, Csz, PL, WL, PL);

    // 7) l2norm q,k (fp16 in/out); V -> fp16 transposed
    l2norm_f16_k<<<Msz, 256>>>(gb,      ga);
    l2norm_f16_k<<<Msz, 256>>>(gb + PL, ga + PL);
    vtrans_k<<<dim3(Ssz/32, Bsz*Hn*2), btr>>>(gb + 2*PL, vb);

    // 8) out-proj weight -> [N,K] fp16
    cvt_trans3_k<<<dim3(Csz/32, Csz/32, 1), btr>>>(wo, wo, wo, gw, Csz, Csz);

    // 9) attention -> plain fp16 output
    attn2_k<<<dim3(Ssz/128, Bsz*Hn), 256, ATT_SMEM>>>(
        ga, ga + PL, vb, mask, go);

    // 10) out = attn_out @ wo + bo (fp32 out)
    gemm_f16_k<0,0><<<ggemm1, 256, GEMM_SMEM>>>(
        go, gw, bo, bo, bo, out,
        Msz, Csz, Csz, 0, 0, 0);
}

// round 16
// speedup vs baseline: 1.0648x; 1.0648x over previous
#include <cuda_runtime.h>
#include <cuda_fp16.h>
#include <math.h>
#include <cstdint>

#define Bsz 4
#define Ssz 2048
#define Csz 1024
#define Hn  16
#define Dh  64
#define Msz (Bsz*Ssz)   // 8192

// Scratch (all fp16)
__device__ __half g_a[3][(size_t)Msz*Csz];        // activation planes A
__device__ __half g_b[3][(size_t)Msz*Csz];        // activation planes B
__device__ __half g_o[(size_t)Msz*Csz];           // attention output
__device__ __half g_vb[(size_t)Msz*Csz];          // V^T per (b,h): [d][s]
__device__ __half g_w[3][(size_t)Csz*Csz];        // weights [N,K]

// ---------------------------------------------------------------------------
// PTX helpers
// ---------------------------------------------------------------------------
__device__ __forceinline__ uint32_t smem_u32(const void* p) {
    uint32_t a;
    asm("{ .reg .u64 t; cvta.to.shared.u64 t, %1; cvt.u32.u64 %0, t; }" : "=r"(a) : "l"(p));
    return a;
}
__device__ __forceinline__ void cp16(uint32_t saddr, const void* g) {
    asm volatile("cp.async.cg.shared.global [%0], [%1], 16;" :: "r"(saddr), "l"(g));
}
__device__ __forceinline__ void cp4(uint32_t saddr, const void* g) {
    asm volatile("cp.async.ca.shared.global [%0], [%1], 4;" :: "r"(saddr), "l"(g));
}
#define CP_COMMIT() asm volatile("cp.async.commit_group;" ::: "memory")
#define CP_WAIT1()  asm volatile("cp.async.wait_group 1;" ::: "memory")
#define CP_WAIT0()  asm volatile("cp.async.wait_group 0;" ::: "memory")

#define LDSM4(r, addr)                                                          \
    asm volatile("ldmatrix.sync.aligned.m8n8.x4.shared.b16 {%0,%1,%2,%3}, [%4];" \
        : "=r"((r)[0]), "=r"((r)[1]), "=r"((r)[2]), "=r"((r)[3]) : "r"(addr))
#define LDSM2(r, addr)                                                          \
    asm volatile("ldmatrix.sync.aligned.m8n8.x2.shared.b16 {%0,%1}, [%2];"      \
        : "=r"((r)[0]), "=r"((r)[1]) : "r"(addr))

#define MMA16816(d, a, b)                                                       \
    asm volatile("mma.sync.aligned.m16n8k16.row.col.f32.f16.f16.f32 "           \
        "{%0,%1,%2,%3}, {%4,%5,%6,%7}, {%8,%9}, {%0,%1,%2,%3};"                 \
        : "+f"((d)[0]), "+f"((d)[1]), "+f"((d)[2]), "+f"((d)[3])                \
        : "r"((a)[0]), "r"((a)[1]), "r"((a)[2]), "r"((a)[3]),                   \
          "r"((b)[0]), "r"((b)[1]))

__device__ __forceinline__ uint32_t pack_f16(float lo, float hi) {
    uint32_t r;
    asm("cvt.rn.f16x2.f32 %0, %1, %2;" : "=r"(r) : "f"(hi), "f"(lo));
    return r;
}

// Swizzled smem offset for a [rows x 32] f16 tile (64B rows): granule g 0..3
__device__ __forceinline__ uint32_t tswz(int r, int g) {
    return (uint32_t)(r * 64 + ((g ^ ((r >> 1) & 3)) & 3) * 16);
}
// Swizzled offset for 128B rows (64 f16): granule g 0..7
__device__ __forceinline__ uint32_t tswz128(int r, int g) {
    return (uint32_t)(r * 128 + ((g ^ (r & 7)) & 7) * 16);
}

// ---------------------------------------------------------------------------
// Convert fp32 -> fp16 (plain)
// ---------------------------------------------------------------------------
__global__ void cvt_f16_k(const float* __restrict__ in, __half* __restrict__ out)
{
    const size_t i4 = (size_t)blockIdx.x * blockDim.x + threadIdx.x;
    float4 v = *(const float4*)(in + i4 * 4);
    *(__half2*)(out + i4*4)     = __floats2half2_rn(v.x, v.y);
    *(__half2*)(out + i4*4 + 2) = __floats2half2_rn(v.z, v.w);
}

// Batched plain convert of 3 weight matrices [N,K] fp32 -> fp16
__global__ void cvt3_k(const float* __restrict__ p0, const float* __restrict__ p1,
                       const float* __restrict__ p2, __half* __restrict__ out)
{
    const int z = blockIdx.y;
    const float* in = (z == 0) ? p0 : ((z == 1) ? p1 : p2);
    __half* o = out + (size_t)z * Csz * Csz;
    const size_t i4 = (size_t)blockIdx.x * blockDim.x + threadIdx.x;
    float4 v = *(const float4*)(in + i4 * 4);
    *(__half2*)(o + i4*4)     = __floats2half2_rn(v.x, v.y);
    *(__half2*)(o + i4*4 + 2) = __floats2half2_rn(v.z, v.w);
}

// ---------------------------------------------------------------------------
// Batched transpose+convert: W[K,N] fp32 -> [N,K] fp16 (z = blockIdx.z)
// ---------------------------------------------------------------------------
__global__ void cvt_trans3_k(const float* __restrict__ p0, const float* __restrict__ p1,
                             const float* __restrict__ p2, __half* __restrict__ out,
                             int K, int N)
{
    __shared__ float t[32][33];
    const int z = blockIdx.z;
    const float* W = (z == 0) ? p0 : ((z == 1) ? p1 : p2);
    __half* o = out + (size_t)z * K * N;
    const int k0 = blockIdx.y * 32, n0 = blockIdx.x * 32;
    const int tx = threadIdx.x, ty = threadIdx.y;
#pragma unroll
    for (int r = 0; r < 4; r++)
        t[ty + r*8][tx] = W[(size_t)(k0 + ty + r*8) * N + n0 + tx];
    __syncthreads();
#pragma unroll
    for (int r = 0; r < 4; r++) {
        const int n = n0 + ty + r*8, k = k0 + tx;
        o[(size_t)n * K + k] = __float2half_rn(t[tx][ty + r*8]);
    }
}

// ---------------------------------------------------------------------------
// V transpose (fp16 in): in [B,S,C] -> vt[(bh*64 + d)*Ssz + s]
// ---------------------------------------------------------------------------
__global__ void vtrans_k(const __half* __restrict__ in, __half* __restrict__ vt)
{
    __shared__ float t[32][33];
    const int z = blockIdx.y;
    const int dblk = z & 1, bh = z >> 1;
    const int b = bh >> 4, h = bh & 15;
    const int s0 = blockIdx.x * 32;
    const int tx = threadIdx.x, ty = threadIdx.y;
#pragma unroll
    for (int r = 0; r < 4; r++)
        t[ty + r*8][tx] = __half2float(
            in[(size_t)(b*Ssz + s0 + ty + r*8) * Csz + h*Dh + dblk*32 + tx]);
    __syncthreads();
#pragma unroll
    for (int r = 0; r < 4; r++) {
        const int d = dblk*32 + ty + r*8;
        vt[((size_t)bh * Dh + d) * Ssz + s0 + tx] = __float2half_rn(t[tx][ty + r*8]);
    }
}

// ---------------------------------------------------------------------------
// Plain fp16 GEMM on mma.sync, batched over blockIdx.z.
// C[M,N] = act(A @ B^T + bias); OUTH selects fp16 vs fp32 output.
// 128x128 tile, BK=32, 256 threads, 2-stage cp.async pipeline.
// ---------------------------------------------------------------------------
#define G_STG 16384
__device__ __forceinline__ void stage_load(
    const __half* __restrict__ A, const __half* __restrict__ B,
    int K, int m0, int n0, int k0, uint32_t sb)
{
    const int t = threadIdx.x;
    const int r = t >> 1;
    const int g0 = (t & 1) * 2;
    const size_t arow = (size_t)(m0 + r) * K + k0;
    const size_t brow = (size_t)(n0 + r) * K + k0;
#pragma unroll
    for (int gg = 0; gg < 2; gg++) {
        const int g = g0 + gg;
        const uint32_t so = tswz(r, g);
        cp16(sb + so,        A + arow + g*8);
        cp16(sb + 8192 + so, B + brow + g*8);
    }
}

template<int ACT, int OUTH>
__global__ __launch_bounds__(256, 1) void gemm_f16_k(
    const __half* __restrict__ A_, const __half* __restrict__ B_,
    const float* __restrict__ bias0, const float* __restrict__ bias1,
    const float* __restrict__ bias2,
    void* __restrict__ C_,
    int M, int N, int K, size_t strideA, size_t strideB, size_t strideC)
{
    extern __shared__ char sm_[];
    const uint32_t sbase = smem_u32(sm_);
    const int tid  = threadIdx.x;
    const int lane = tid & 31;
    const int warp = tid >> 5;
    const int wm = warp >> 2;
    const int wn = warp & 3;
    const int m0 = blockIdx.y * 128, n0 = blockIdx.x * 128;
    const int z  = blockIdx.z;

    const __half* A = A_ + (size_t)z * strideA;
    const __half* B = B_ + (size_t)z * strideB;
    const float* bias = (z == 0) ? bias0 : ((z == 1) ? bias1 : bias2);

    float acc[4][4][4];
#pragma unroll
    for (int i = 0; i < 4; i++)
#pragma unroll
        for (int j = 0; j < 4; j++)
#pragma unroll
            for (int c = 0; c < 4; c++) acc[i][j][c] = 0.f;

    const int NIT = K >> 5;

    stage_load(A, B, K, m0, n0, 0, sbase);
    CP_COMMIT();

    for (int it = 0; it < NIT; it++) {
        if (it + 1 < NIT) {
            stage_load(A, B, K, m0, n0, (it+1) << 5,
                       sbase + ((it+1) & 1) * G_STG);
            CP_COMMIT();
            CP_WAIT1();
        } else {
            CP_WAIT0();
        }
        __syncthreads();

        const uint32_t sb = sbase + (it & 1) * G_STG;
        const int lr  = lane & 15;
        const int hf  = lane >> 4;
        const int lnb = lane & 7;
        const int hfb = (lane >> 3) & 1;

#pragma unroll
        for (int kk = 0; kk < 2; kk++) {
            uint32_t ah[4][4], bfr[4][2];
#pragma unroll
            for (int mt = 0; mt < 4; mt++) {
                const int r = wm*64 + mt*16 + lr;
                LDSM4(ah[mt], sb + tswz(r, kk*2 + hf));
            }
#pragma unroll
            for (int nt = 0; nt < 4; nt++) {
                const int rn = wn*32 + nt*8 + lnb;
                LDSM2(bfr[nt], sb + 8192 + tswz(rn, kk*2 + hfb));
            }
#pragma unroll
            for (int mt = 0; mt < 4; mt++)
#pragma unroll
                for (int nt = 0; nt < 4; nt++)
                    MMA16816(acc[mt][nt], ah[mt], bfr[nt]);
        }
        __syncthreads();
    }

    const int gid = lane >> 2;
    const int tg  = lane & 3;
    float*  Cf = (float*)C_  + (size_t)z * strideC;
    __half* Ch = (__half*)C_ + (size_t)z * strideC;
#pragma unroll
    for (int mt = 0; mt < 4; mt++) {
#pragma unroll
        for (int nt = 0; nt < 4; nt++) {
            const int ncol = n0 + wn*32 + nt*8 + tg*2;
            const float b0 = __ldg(&bias[ncol]);
            const float b1 = __ldg(&bias[ncol + 1]);
#pragma unroll
            for (int h = 0; h < 2; h++) {
                const int row = m0 + wm*64 + mt*16 + gid + h*8;
                float v0 = acc[mt][nt][h*2 + 0] + b0;
                float v1 = acc[mt][nt][h*2 + 1] + b1;
                if (ACT) {
                    v0 = v0 / (1.f + __expf(-v0));
                    v1 = v1 / (1.f + __expf(-v1));
                }
                if (OUTH) {
                    *(__half2*)(Ch + (size_t)row * N + ncol) = __floats2half2_rn(v0, v1);
                } else {
                    *(float2*)(Cf + (size_t)row * N + ncol) = make_float2(v0, v1);
                }
            }
        }
    }
}

// ---------------------------------------------------------------------------
// Fused depthwise conv k=3, fp16 in -> fp16 out. Batched over z. 8-wide.
// Weight loads vectorized: 6x float4 (dw) + 2x float4 (dwb) per thread.
// ---------------------------------------------------------------------------
__global__ void dwconv_f16_k(
    const __half* __restrict__ in_,
    const float* __restrict__ dw0, const float* __restrict__ dw1, const float* __restrict__ dw2,
    const float* __restrict__ db0, const float* __restrict__ db1, const float* __restrict__ db2,
    __half* __restrict__ out_)
{
    const int z = blockIdx.y;
    const __half* in = in_ + (size_t)z * Msz * Csz;
    const float* dw  = (z == 0) ? dw0 : ((z == 1) ? dw1 : dw2);
    const float* dwb = (z == 0) ? db0 : ((z == 1) ? db1 : db2);
    __half* out = out_ + (size_t)z * Msz * Csz;

    const int idx = blockIdx.x * blockDim.x + threadIdx.x;   // over Msz*Csz/8
    const int c8 = (idx & (Csz/8 - 1)) * 8;
    const int m  = idx >> 7;
    const int s  = m & (Ssz - 1);

    // Vectorized weights: dw[c8*3 .. c8*3+23] (96B, 16B-aligned), dwb[c8..c8+7]
    float wreg[24], bb[8];
    const float4* dwv = (const float4*)(dw + c8*3);
#pragma unroll
    for (int i = 0; i < 6; i++) *(float4*)&wreg[i*4] = __ldg(&dwv[i]);
    *(float4*)&bb[0] = __ldg((const float4*)(dwb + c8));
    *(float4*)&bb[4] = __ldg((const float4*)(dwb + c8 + 4));

    uint4 zz = make_uint4(0,0,0,0);
    uint4 x0 = (s > 0)       ? *(const uint4*)(in + (size_t)(m-1)*Csz + c8) : zz;
    uint4 x1 =                 *(const uint4*)(in + (size_t)m*Csz + c8);
    uint4 x2 = (s < Ssz - 1) ? *(const uint4*)(in + (size_t)(m+1)*Csz + c8) : zz;

    const __half* h0 = (const __half*)&x0;
    const __half* h1 = (const __half*)&x1;
    const __half* h2 = (const __half*)&x2;
    __half res[8];
#pragma unroll
    for (int t = 0; t < 8; t++) {
        const float v = bb[t] + wreg[t*3+0]*__half2float(h0[t])
                              + wreg[t*3+1]*__half2float(h1[t])
                              + wreg[t*3+2]*__half2float(h2[t]);
        res[t] = __float2half_rn(v);
    }
    *(uint4*)(out + (size_t)m*Csz + c8) = *(uint4*)res;
}

// ---------------------------------------------------------------------------
// L2 normalize over C=1024, fp16 in -> fp16 out.
// ---------------------------------------------------------------------------
__global__ void l2norm_f16_k(const __half* __restrict__ src, __half* __restrict__ dst)
{
    __shared__ float red[8];
    const __half* p = src + (size_t)blockIdx.x * Csz;
    __half2 a = *(const __half2*)(p + threadIdx.x*4);
    __half2 b = *(const __half2*)(p + threadIdx.x*4 + 2);
    float2 fa = __half22float2(a), fb = __half22float2(b);
    float ss = fa.x*fa.x + fa.y*fa.y + fb.x*fb.x + fb.y*fb.y;
#pragma unroll
    for (int off = 16; off; off >>= 1) ss += __shfl_xor_sync(0xffffffffu, ss, off);
    if ((threadIdx.x & 31) == 0) red[threadIdx.x >> 5] = ss;
    __syncthreads();
    if (threadIdx.x == 0) {
        float t = 0.f;
#pragma unroll
        for (int i = 0; i < 8; i++) t += red[i];
        red[0] = t;
    }
    __syncthreads();
    const float inv = 1.0f / fmaxf(sqrtf(red[0]), 1e-12f);
    __half* d = dst + (size_t)blockIdx.x * Csz + threadIdx.x*4;
    *(__half2*)(d)     = __floats2half2_rn(fa.x*inv, fa.y*inv);
    *(__half2*)(d + 2) = __floats2half2_rn(fb.x*inv, fb.y*inv);
}

// ---------------------------------------------------------------------------
// Flash attention on mma.sync (fp16 in, fp32 accum). Output plain fp16.
// ---------------------------------------------------------------------------
#define ATT_STG 16640
__device__ __forceinline__ void attn_stage(
    const __half* __restrict__ kb, const __half* __restrict__ vt,
    const int* __restrict__ mask, size_t qkbase, size_t vbase, int b,
    int chunk, uint32_t st)
{
    const int tid = threadIdx.x;
#pragma unroll
    for (int i = 0; i < 2; i++) {
        const int idx = tid + i*256;
        const int r = idx >> 3, g = idx & 7;
        const uint32_t so = tswz128(r, g);
        cp16(st + so,        kb + qkbase + (size_t)(chunk*64 + r) * Csz + g*8);
        cp16(st + 8192 + so, vt + vbase + (size_t)r * Ssz + chunk*64 + g*8);
    }
    if (tid < 64)
        cp4(st + 16384 + tid*4, mask + (size_t)b * Ssz + chunk*64 + tid);
}

__global__ __launch_bounds__(256, 1) void attn2_k(
    const __half* __restrict__ qb, const __half* __restrict__ kb,
    const __half* __restrict__ vt, const int* __restrict__ mask,
    __half* __restrict__ og)
{
    extern __shared__ char sm_[];
    const uint32_t sbase = smem_u32(sm_);
    const int tid = threadIdx.x, lane = tid & 31, warp = tid >> 5;
    const int q0 = blockIdx.x * 128;
    const int bh = blockIdx.y;
    const int b = bh >> 4, h = bh & 15;

    const size_t qkbase = ((size_t)b * Ssz) * Csz + h * Dh;
    const size_t vbase  = (size_t)bh * Dh * Ssz;

#pragma unroll
    for (int i = 0; i < 4; i++) {
        const int idx = tid + i*256;
        const int r = idx >> 3, g = idx & 7;
        cp16(sbase + tswz128(r, g), qb + qkbase + (size_t)(q0 + r) * Csz + g*8);
    }
    CP_COMMIT();

    const uint32_t kvb = sbase + 16384;
    attn_stage(kb, vt, mask, qkbase, vbase, b, 0, kvb);
    CP_COMMIT();

    float oacc[8][4];
#pragma unroll
    for (int nt = 0; nt < 8; nt++)
#pragma unroll
        for (int c = 0; c < 4; c++) oacc[nt][c] = 0.f;
    float m0 = -1e30f, m1 = -1e30f, l0 = 0.f, l1 = 0.f;
    uint32_t aq[4][4];

    const int cb = (lane & 3) * 2;

    for (int it = 0; it < Ssz/64; it++) {
        if (it + 1 < Ssz/64) {
            attn_stage(kb, vt, mask, qkbase, vbase, b, it+1, kvb + ((it+1)&1)*ATT_STG);
            CP_COMMIT();
            CP_WAIT1();
        } else {
            CP_WAIT0();
        }
        __syncthreads();

        if (it == 0) {
#pragma unroll
            for (int ks = 0; ks < 4; ks++) {
                const int r = warp*16 + (lane & 15);
                const int g = ks*2 + (lane >> 4);
                LDSM4(aq[ks], sbase + tswz128(r, g));
            }
        }

        const uint32_t st = kvb + (it & 1) * ATT_STG;
        const int* Ms = (const int*)(sm_ + 16384 + (it & 1) * ATT_STG + 16384);

        float sacc[8][4];
#pragma unroll
        for (int nt = 0; nt < 8; nt++)
#pragma unroll
            for (int c = 0; c < 4; c++) sacc[nt][c] = 0.f;

#pragma unroll
        for (int ks = 0; ks < 4; ks++) {
#pragma unroll
            for (int nt = 0; nt < 8; nt++) {
                uint32_t kf[2];
                const int r = nt*8 + (lane & 7);
                const int g = ks*2 + ((lane >> 3) & 1);
                LDSM2(kf, st + tswz128(r, g));
                MMA16816(sacc[nt], aq[ks], kf);
            }
        }

        float mx0 = -1e30f, mx1 = -1e30f;
#pragma unroll
        for (int nt = 0; nt < 8; nt++) {
            const int c = nt*8 + cb;
            const bool k0m = Ms[c] != 0, k1m = Ms[c+1] != 0;
            sacc[nt][0] = k0m ? sacc[nt][0]*0.125f : -1e30f;
            sacc[nt][1] = k1m ? sacc[nt][1]*0.125f : -1e30f;
            sacc[nt][2] = k0m ? sacc[nt][2]*0.125f : -1e30f;
            sacc[nt][3] = k1m ? sacc[nt][3]*0.125f : -1e30f;
            mx0 = fmaxf(mx0, fmaxf(sacc[nt][0], sacc[nt][1]));
            mx1 = fmaxf(mx1, fmaxf(sacc[nt][2], sacc[nt][3]));
        }
        mx0 = fmaxf(mx0, __shfl_xor_sync(0xffffffffu, mx0, 1));
        mx0 = fmaxf(mx0, __shfl_xor_sync(0xffffffffu, mx0, 2));
        mx1 = fmaxf(mx1, __shfl_xor_sync(0xffffffffu, mx1, 1));
        mx1 = fmaxf(mx1, __shfl_xor_sync(0xffffffffu, mx1, 2));
        const float mn0 = fmaxf(m0, mx0), mn1 = fmaxf(m1, mx1);
        const float c0 = __expf(m0 - mn0), c1 = __expf(m1 - mn1);
        m0 = mn0; m1 = mn1;
        float rs0 = 0.f, rs1 = 0.f;
#pragma unroll
        for (int nt = 0; nt < 8; nt++) {
            sacc[nt][0] = __expf(sacc[nt][0] - mn0);
            sacc[nt][1] = __expf(sacc[nt][1] - mn0);
            sacc[nt][2] = __expf(sacc[nt][2] - mn1);
            sacc[nt][3] = __expf(sacc[nt][3] - mn1);
            rs0 += sacc[nt][0] + sacc[nt][1];
            rs1 += sacc[nt][2] + sacc[nt][3];
        }
        rs0 += __shfl_xor_sync(0xffffffffu, rs0, 1);
        rs0 += __shfl_xor_sync(0xffffffffu, rs0, 2);
        rs1 += __shfl_xor_sync(0xffffffffu, rs1, 1);
        rs1 += __shfl_xor_sync(0xffffffffu, rs1, 2);
        l0 = l0*c0 + rs0;
        l1 = l1*c1 + rs1;
#pragma unroll
        for (int nt = 0; nt < 8; nt++) {
            oacc[nt][0] *= c0; oacc[nt][1] *= c0;
            oacc[nt][2] *= c1; oacc[nt][3] *= c1;
        }

#pragma unroll
        for (int ks = 0; ks < 4; ks++) {
            uint32_t pa[4];
            pa[0] = pack_f16(sacc[2*ks][0],   sacc[2*ks][1]);
            pa[1] = pack_f16(sacc[2*ks][2],   sacc[2*ks][3]);
            pa[2] = pack_f16(sacc[2*ks+1][0], sacc[2*ks+1][1]);
            pa[3] = pack_f16(sacc[2*ks+1][2], sacc[2*ks+1][3]);
#pragma unroll
            for (int nt = 0; nt < 8; nt++) {
                uint32_t vf[2];
                const int r = nt*8 + (lane & 7);
                const int g = ks*2 + ((lane >> 3) & 1);
                LDSM2(vf, st + 8192 + tswz128(r, g));
                MMA16816(oacc[nt], pa, vf);
            }
        }
        __syncthreads();
    }

    const float inv0 = 1.f / l0, inv1 = 1.f / l1;
    const int r0 = q0 + warp*16 + (lane >> 2);
#pragma unroll
    for (int nt = 0; nt < 8; nt++) {
        const int c = h*Dh + nt*8 + cb;
        *(__half2*)(og + ((size_t)b*Ssz + r0) * Csz + c) =
            __floats2half2_rn(oacc[nt][0]*inv0, oacc[nt][1]*inv0);
        *(__half2*)(og + ((size_t)b*Ssz + r0 + 8) * Csz + c) =
            __floats2half2_rn(oacc[nt][2]*inv1, oacc[nt][3]*inv1);
    }
}

// ---------------------------------------------------------------------------
extern "C" void kernel_launch(void* const* d_in, const int* in_sizes, int n_in,
                              void* d_out, int out_size)
{
    const float* x    = (const float*)d_in[0];
    const int*   mask = (const int*)  d_in[1];
    const float* W[3]   = {(const float*)d_in[2],  (const float*)d_in[8],  (const float*)d_in[14]};
    const float* Bi[3]  = {(const float*)d_in[3],  (const float*)d_in[9],  (const float*)d_in[15]};
    const float* DW[3]  = {(const float*)d_in[4],  (const float*)d_in[10], (const float*)d_in[16]};
    const float* DWB[3] = {(const float*)d_in[5],  (const float*)d_in[11], (const float*)d_in[17]};
    const float* PW[3]  = {(const float*)d_in[6],  (const float*)d_in[12], (const float*)d_in[18]};
    const float* PWB[3] = {(const float*)d_in[7],  (const float*)d_in[13], (const float*)d_in[19]};
    const float* wo = (const float*)d_in[20];
    const float* bo = (const float*)d_in[21];
    float* out = (float*)d_out;

    __half *ga, *gb, *go, *vb, *gw;
    cudaGetSymbolAddress((void**)&ga, g_a);
    cudaGetSymbolAddress((void**)&gb, g_b);
    cudaGetSymbolAddress((void**)&go, g_o);
    cudaGetSymbolAddress((void**)&vb, g_vb);
    cudaGetSymbolAddress((void**)&gw, g_w);
    const size_t PL = (size_t)Msz * Csz;
    const size_t WL = (size_t)Csz * Csz;

    const int GEMM_SMEM = 2 * G_STG;            // 32768
    const int ATT_SMEM  = 16384 + 2*ATT_STG;    // 49664
    cudaFuncSetAttribute(gemm_f16_k<0,0>, cudaFuncAttributeMaxDynamicSharedMemorySize, GEMM_SMEM);
    cudaFuncSetAttribute(gemm_f16_k<0,1>, cudaFuncAttributeMaxDynamicSharedMemorySize, GEMM_SMEM);
    cudaFuncSetAttribute(gemm_f16_k<1,1>, cudaFuncAttributeMaxDynamicSharedMemorySize, GEMM_SMEM);
    cudaFuncSetAttribute(attn2_k, cudaFuncAttributeMaxDynamicSharedMemorySize, ATT_SMEM);

    const dim3 ggemm1(Csz/128, Msz/128, 1);
    const dim3 ggemm3(Csz/128, Msz/128, 3);
    const dim3 gtr3(Csz/32, Csz/32, 3), btr(32, 8);

    // 1) x -> fp16 (ga0)
    cvt_f16_k<<<(Msz*Csz/4)/256, 256>>>(x, ga);

    // 2) QKV weights -> [N,K] fp16 (batched)
    cvt_trans3_k<<<gtr3, btr>>>(W[0], W[1], W[2], gw, Csz, Csz);

    // 3) batched QKV GEMM: q/k/v = silu(x @ W + b) -> gb[z] (fp16)
    gemm_f16_k<1,1><<<ggemm3, 256, GEMM_SMEM>>>(
        ga, gw, Bi[0], Bi[1], Bi[2], gb,
        Msz, Csz, Csz, 0, WL, PL);

    // 4) depthwise conv fp16->fp16: gb[z] -> ga[z]
    dwconv_f16_k<<<dim3((Msz*Csz/8)/256, 3), 256>>>(
        gb, DW[0], DW[1], DW[2], DWB[0], DWB[1], DWB[2], ga);

    // 5) pointwise weights (already [N,K]) -> fp16 (batched)
    cvt3_k<<<dim3((Csz*Csz/4)/256, 3), 256>>>(PW[0], PW[1], PW[2], gw);

    // 6) batched pointwise GEMM -> gb[z] (fp16)
    gemm_f16_k<0,1><<<ggemm3, 256, GEMM_SMEM>>>(
        ga, gw, PWB[0], PWB[1], PWB[2], gb,
        Msz, Csz, Csz, PL, WL, PL);

    // 7) l2norm q,k (fp16 in/out); V -> fp16 transposed
    l2norm_f16_k<<<Msz, 256>>>(gb,      ga);
    l2norm_f16_k<<<Msz, 256>>>(gb + PL, ga + PL);
    vtrans_k<<<dim3(Ssz/32, Bsz*Hn*2), btr>>>(gb + 2*PL, vb);

    // 8) out-proj weight -> [N,K] fp16
    cvt_trans3_k<<<dim3(Csz/32, Csz/32, 1), btr>>>(wo, wo, wo, gw, Csz, Csz);

    // 9) attention -> plain fp16 output
    attn2_k<<<dim3(Ssz/128, Bsz*Hn), 256, ATT_SMEM>>>(
        ga, ga + PL, vb, mask, go);

    // 10) out = attn_out @ wo + bo (fp32 out)
    gemm_f16_k<0,0><<<ggemm1, 256, GEMM_SMEM>>>(
        go, gw, bo, bo, bo, out,
        Msz, Csz, Csz, 0, 0, 0);
}

// round 17
// speedup vs baseline: 1.0699x; 1.0048x over previous
#include <cuda_runtime.h>
#include <cuda_fp16.h>
#include <math.h>
#include <cstdint>

#define Bsz 4
#define Ssz 2048
#define Csz 1024
#define Hn  16
#define Dh  64
#define Msz (Bsz*Ssz)   // 8192

// Scratch (all fp16)
__device__ __half g_a[3][(size_t)Msz*Csz];        // activation planes A
__device__ __half g_b[3][(size_t)Msz*Csz];        // activation planes B
__device__ __half g_o[(size_t)Msz*Csz];           // attention output
__device__ __half g_vb[(size_t)Msz*Csz];          // V^T per (b,h): [d][s]
__device__ __half g_w[3][(size_t)Csz*Csz];        // weights [N,K]

// ---------------------------------------------------------------------------
// PTX helpers
// ---------------------------------------------------------------------------
__device__ __forceinline__ uint32_t smem_u32(const void* p) {
    uint32_t a;
    asm("{ .reg .u64 t; cvta.to.shared.u64 t, %1; cvt.u32.u64 %0, t; }" : "=r"(a) : "l"(p));
    return a;
}
__device__ __forceinline__ void cp16(uint32_t saddr, const void* g) {
    asm volatile("cp.async.cg.shared.global [%0], [%1], 16;" :: "r"(saddr), "l"(g));
}
__device__ __forceinline__ void cp4(uint32_t saddr, const void* g) {
    asm volatile("cp.async.ca.shared.global [%0], [%1], 4;" :: "r"(saddr), "l"(g));
}
#define CP_COMMIT() asm volatile("cp.async.commit_group;" ::: "memory")
#define CP_WAIT1()  asm volatile("cp.async.wait_group 1;" ::: "memory")
#define CP_WAIT0()  asm volatile("cp.async.wait_group 0;" ::: "memory")

#define LDSM4(r, addr)                                                          \
    asm volatile("ldmatrix.sync.aligned.m8n8.x4.shared.b16 {%0,%1,%2,%3}, [%4];" \
        : "=r"((r)[0]), "=r"((r)[1]), "=r"((r)[2]), "=r"((r)[3]) : "r"(addr))
#define LDSM2(r, addr)                                                          \
    asm volatile("ldmatrix.sync.aligned.m8n8.x2.shared.b16 {%0,%1}, [%2];"      \
        : "=r"((r)[0]), "=r"((r)[1]) : "r"(addr))

#define MMA16816(d, a, b)                                                       \
    asm volatile("mma.sync.aligned.m16n8k16.row.col.f32.f16.f16.f32 "           \
        "{%0,%1,%2,%3}, {%4,%5,%6,%7}, {%8,%9}, {%0,%1,%2,%3};"                 \
        : "+f"((d)[0]), "+f"((d)[1]), "+f"((d)[2]), "+f"((d)[3])                \
        : "r"((a)[0]), "r"((a)[1]), "r"((a)[2]), "r"((a)[3]),                   \
          "r"((b)[0]), "r"((b)[1]))

__device__ __forceinline__ uint32_t pack_f16(float lo, float hi) {
    uint32_t r;
    asm("cvt.rn.f16x2.f32 %0, %1, %2;" : "=r"(r) : "f"(hi), "f"(lo));
    return r;
}

// Swizzled smem offset for a [rows x 32] f16 tile (64B rows): granule g 0..3
__device__ __forceinline__ uint32_t tswz(int r, int g) {
    return (uint32_t)(r * 64 + ((g ^ ((r >> 1) & 3)) & 3) * 16);
}
// Swizzled offset for 128B rows (64 f16): granule g 0..7
__device__ __forceinline__ uint32_t tswz128(int r, int g) {
    return (uint32_t)(r * 128 + ((g ^ (r & 7)) & 7) * 16);
}

// ---------------------------------------------------------------------------
// Convert fp32 -> fp16 (plain)
// ---------------------------------------------------------------------------
__global__ void cvt_f16_k(const float* __restrict__ in, __half* __restrict__ out)
{
    const size_t i4 = (size_t)blockIdx.x * blockDim.x + threadIdx.x;
    float4 v = *(const float4*)(in + i4 * 4);
    *(__half2*)(out + i4*4)     = __floats2half2_rn(v.x, v.y);
    *(__half2*)(out + i4*4 + 2) = __floats2half2_rn(v.z, v.w);
}

// Batched plain convert of 3 weight matrices [N,K] fp32 -> fp16
__global__ void cvt3_k(const float* __restrict__ p0, const float* __restrict__ p1,
                       const float* __restrict__ p2, __half* __restrict__ out)
{
    const int z = blockIdx.y;
    const float* in = (z == 0) ? p0 : ((z == 1) ? p1 : p2);
    __half* o = out + (size_t)z * Csz * Csz;
    const size_t i4 = (size_t)blockIdx.x * blockDim.x + threadIdx.x;
    float4 v = *(const float4*)(in + i4 * 4);
    *(__half2*)(o + i4*4)     = __floats2half2_rn(v.x, v.y);
    *(__half2*)(o + i4*4 + 2) = __floats2half2_rn(v.z, v.w);
}

// ---------------------------------------------------------------------------
// Batched transpose+convert: W[K,N] fp32 -> [N,K] fp16 (z = blockIdx.z)
// ---------------------------------------------------------------------------
__global__ void cvt_trans3_k(const float* __restrict__ p0, const float* __restrict__ p1,
                             const float* __restrict__ p2, __half* __restrict__ out,
                             int K, int N)
{
    __shared__ float t[32][33];
    const int z = blockIdx.z;
    const float* W = (z == 0) ? p0 : ((z == 1) ? p1 : p2);
    __half* o = out + (size_t)z * K * N;
    const int k0 = blockIdx.y * 32, n0 = blockIdx.x * 32;
    const int tx = threadIdx.x, ty = threadIdx.y;
#pragma unroll
    for (int r = 0; r < 4; r++)
        t[ty + r*8][tx] = W[(size_t)(k0 + ty + r*8) * N + n0 + tx];
    __syncthreads();
#pragma unroll
    for (int r = 0; r < 4; r++) {
        const int n = n0 + ty + r*8, k = k0 + tx;
        o[(size_t)n * K + k] = __float2half_rn(t[tx][ty + r*8]);
    }
}

// ---------------------------------------------------------------------------
// V transpose (fp16 in): in [B,S,C] -> vt[(bh*64 + d)*Ssz + s]
// ---------------------------------------------------------------------------
__global__ void vtrans_k(const __half* __restrict__ in, __half* __restrict__ vt)
{
    __shared__ float t[32][33];
    const int z = blockIdx.y;
    const int dblk = z & 1, bh = z >> 1;
    const int b = bh >> 4, h = bh & 15;
    const int s0 = blockIdx.x * 32;
    const int tx = threadIdx.x, ty = threadIdx.y;
#pragma unroll
    for (int r = 0; r < 4; r++)
        t[ty + r*8][tx] = __half2float(
            in[(size_t)(b*Ssz + s0 + ty + r*8) * Csz + h*Dh + dblk*32 + tx]);
    __syncthreads();
#pragma unroll
    for (int r = 0; r < 4; r++) {
        const int d = dblk*32 + ty + r*8;
        vt[((size_t)bh * Dh + d) * Ssz + s0 + tx] = __float2half_rn(t[tx][ty + r*8]);
    }
}

// ---------------------------------------------------------------------------
// Plain fp16 GEMM on mma.sync, batched over blockIdx.z.
// ---------------------------------------------------------------------------
#define G_STG 16384
__device__ __forceinline__ void stage_load(
    const __half* __restrict__ A, const __half* __restrict__ B,
    int K, int m0, int n0, int k0, uint32_t sb)
{
    const int t = threadIdx.x;
    const int r = t >> 1;
    const int g0 = (t & 1) * 2;
    const size_t arow = (size_t)(m0 + r) * K + k0;
    const size_t brow = (size_t)(n0 + r) * K + k0;
#pragma unroll
    for (int gg = 0; gg < 2; gg++) {
        const int g = g0 + gg;
        const uint32_t so = tswz(r, g);
        cp16(sb + so,        A + arow + g*8);
        cp16(sb + 8192 + so, B + brow + g*8);
    }
}

template<int ACT, int OUTH>
__global__ __launch_bounds__(256, 1) void gemm_f16_k(
    const __half* __restrict__ A_, const __half* __restrict__ B_,
    const float* __restrict__ bias0, const float* __restrict__ bias1,
    const float* __restrict__ bias2,
    void* __restrict__ C_,
    int M, int N, int K, size_t strideA, size_t strideB, size_t strideC)
{
    extern __shared__ char sm_[];
    const uint32_t sbase = smem_u32(sm_);
    const int tid  = threadIdx.x;
    const int lane = tid & 31;
    const int warp = tid >> 5;
    const int wm = warp >> 2;
    const int wn = warp & 3;
    const int m0 = blockIdx.y * 128, n0 = blockIdx.x * 128;
    const int z  = blockIdx.z;

    const __half* A = A_ + (size_t)z * strideA;
    const __half* B = B_ + (size_t)z * strideB;
    const float* bias = (z == 0) ? bias0 : ((z == 1) ? bias1 : bias2);

    float acc[4][4][4];
#pragma unroll
    for (int i = 0; i < 4; i++)
#pragma unroll
        for (int j = 0; j < 4; j++)
#pragma unroll
            for (int c = 0; c < 4; c++) acc[i][j][c] = 0.f;

    const int NIT = K >> 5;

    stage_load(A, B, K, m0, n0, 0, sbase);
    CP_COMMIT();

    for (int it = 0; it < NIT; it++) {
        if (it + 1 < NIT) {
            stage_load(A, B, K, m0, n0, (it+1) << 5,
                       sbase + ((it+1) & 1) * G_STG);
            CP_COMMIT();
            CP_WAIT1();
        } else {
            CP_WAIT0();
        }
        __syncthreads();

        const uint32_t sb = sbase + (it & 1) * G_STG;
        const int lr  = lane & 15;
        const int hf  = lane >> 4;
        const int lnb = lane & 7;
        const int hfb = (lane >> 3) & 1;

#pragma unroll
        for (int kk = 0; kk < 2; kk++) {
            uint32_t ah[4][4], bfr[4][2];
#pragma unroll
            for (int mt = 0; mt < 4; mt++) {
                const int r = wm*64 + mt*16 + lr;
                LDSM4(ah[mt], sb + tswz(r, kk*2 + hf));
            }
#pragma unroll
            for (int nt = 0; nt < 4; nt++) {
                const int rn = wn*32 + nt*8 + lnb;
                LDSM2(bfr[nt], sb + 8192 + tswz(rn, kk*2 + hfb));
            }
#pragma unroll
            for (int mt = 0; mt < 4; mt++)
#pragma unroll
                for (int nt = 0; nt < 4; nt++)
                    MMA16816(acc[mt][nt], ah[mt], bfr[nt]);
        }
        __syncthreads();
    }

    const int gid = lane >> 2;
    const int tg  = lane & 3;
    float*  Cf = (float*)C_  + (size_t)z * strideC;
    __half* Ch = (__half*)C_ + (size_t)z * strideC;
#pragma unroll
    for (int mt = 0; mt < 4; mt++) {
#pragma unroll
        for (int nt = 0; nt < 4; nt++) {
            const int ncol = n0 + wn*32 + nt*8 + tg*2;
            const float b0 = __ldg(&bias[ncol]);
            const float b1 = __ldg(&bias[ncol + 1]);
#pragma unroll
            for (int h = 0; h < 2; h++) {
                const int row = m0 + wm*64 + mt*16 + gid + h*8;
                float v0 = acc[mt][nt][h*2 + 0] + b0;
                float v1 = acc[mt][nt][h*2 + 1] + b1;
                if (ACT) {
                    v0 = v0 / (1.f + __expf(-v0));
                    v1 = v1 / (1.f + __expf(-v1));
                }
                if (OUTH) {
                    *(__half2*)(Ch + (size_t)row * N + ncol) = __floats2half2_rn(v0, v1);
                } else {
                    *(float2*)(Cf + (size_t)row * N + ncol) = make_float2(v0, v1);
                }
            }
        }
    }
}

// ---------------------------------------------------------------------------
// Fused depthwise conv k=3, fp16 in -> fp16 out. Batched over z. 8-wide.
// ---------------------------------------------------------------------------
__global__ void dwconv_f16_k(
    const __half* __restrict__ in_,
    const float* __restrict__ dw0, const float* __restrict__ dw1, const float* __restrict__ dw2,
    const float* __restrict__ db0, const float* __restrict__ db1, const float* __restrict__ db2,
    __half* __restrict__ out_)
{
    const int z = blockIdx.y;
    const __half* in = in_ + (size_t)z * Msz * Csz;
    const float* dw  = (z == 0) ? dw0 : ((z == 1) ? dw1 : dw2);
    const float* dwb = (z == 0) ? db0 : ((z == 1) ? db1 : db2);
    __half* out = out_ + (size_t)z * Msz * Csz;

    const int idx = blockIdx.x * blockDim.x + threadIdx.x;
    const int c8 = (idx & (Csz/8 - 1)) * 8;
    const int m  = idx >> 7;
    const int s  = m & (Ssz - 1);

    float wreg[24], bb[8];
    const float4* dwv = (const float4*)(dw + c8*3);
#pragma unroll
    for (int i = 0; i < 6; i++) *(float4*)&wreg[i*4] = __ldg(&dwv[i]);
    *(float4*)&bb[0] = __ldg((const float4*)(dwb + c8));
    *(float4*)&bb[4] = __ldg((const float4*)(dwb + c8 + 4));

    uint4 zz = make_uint4(0,0,0,0);
    uint4 x0 = (s > 0)       ? *(const uint4*)(in + (size_t)(m-1)*Csz + c8) : zz;
    uint4 x1 =                 *(const uint4*)(in + (size_t)m*Csz + c8);
    uint4 x2 = (s < Ssz - 1) ? *(const uint4*)(in + (size_t)(m+1)*Csz + c8) : zz;

    const __half* h0 = (const __half*)&x0;
    const __half* h1 = (const __half*)&x1;
    const __half* h2 = (const __half*)&x2;
    __half res[8];
#pragma unroll
    for (int t = 0; t < 8; t++) {
        const float v = bb[t] + wreg[t*3+0]*__half2float(h0[t])
                              + wreg[t*3+1]*__half2float(h1[t])
                              + wreg[t*3+2]*__half2float(h2[t]);
        res[t] = __float2half_rn(v);
    }
    *(uint4*)(out + (size_t)m*Csz + c8) = *(uint4*)res;
}

// ---------------------------------------------------------------------------
// L2 normalize over C=1024, fp16 in -> fp16 out. Batched over blockIdx.y.
// ---------------------------------------------------------------------------
__global__ void l2norm_f16_k(const __half* __restrict__ src_, __half* __restrict__ dst_,
                             size_t planeStride)
{
    __shared__ float red[8];
    const __half* src = src_ + (size_t)blockIdx.y * planeStride;
    __half* dst = dst_ + (size_t)blockIdx.y * planeStride;
    const __half* p = src + (size_t)blockIdx.x * Csz;
    __half2 a = *(const __half2*)(p + threadIdx.x*4);
    __half2 b = *(const __half2*)(p + threadIdx.x*4 + 2);
    float2 fa = __half22float2(a), fb = __half22float2(b);
    float ss = fa.x*fa.x + fa.y*fa.y + fb.x*fb.x + fb.y*fb.y;
#pragma unroll
    for (int off = 16; off; off >>= 1) ss += __shfl_xor_sync(0xffffffffu, ss, off);
    if ((threadIdx.x & 31) == 0) red[threadIdx.x >> 5] = ss;
    __syncthreads();
    if (threadIdx.x == 0) {
        float t = 0.f;
#pragma unroll
        for (int i = 0; i < 8; i++) t += red[i];
        red[0] = t;
    }
    __syncthreads();
    const float inv = 1.0f / fmaxf(sqrtf(red[0]), 1e-12f);
    __half* d = dst + (size_t)blockIdx.x * Csz + threadIdx.x*4;
    *(__half2*)(d)     = __floats2half2_rn(fa.x*inv, fa.y*inv);
    *(__half2*)(d + 2) = __floats2half2_rn(fb.x*inv, fb.y*inv);
}

// ---------------------------------------------------------------------------
// Flash attention on mma.sync (fp16 in, fp32 accum). KV chunk = 128.
// Stage = K(16KB) + V^T(2x8KB subtiles) + mask(512B) = 33280B.
// smem = Q(16KB) + 2 stages = 82944B.
// ---------------------------------------------------------------------------
#define ATT_STG 33280
__device__ __forceinline__ void attn_stage(
    const __half* __restrict__ kb, const __half* __restrict__ vt,
    const int* __restrict__ mask, size_t qkbase, size_t vbase, int b,
    int chunk, uint32_t st)
{
    const int tid = threadIdx.x;
#pragma unroll
    for (int i = 0; i < 4; i++) {          // K: 128 rows x 8 granules
        const int idx = tid + i*256;
        const int r = idx >> 3, g = idx & 7;
        cp16(st + tswz128(r, g),
             kb + qkbase + (size_t)(chunk*128 + r) * Csz + g*8);
    }
#pragma unroll
    for (int i = 0; i < 4; i++) {          // V^T: 2 subtiles of 64 rows x 8 granules
        const int idx = tid + i*256;
        const int sub = idx >> 9;          // 0 or 1
        const int r = (idx >> 3) & 63, g = idx & 7;
        cp16(st + 16384 + sub*8192 + tswz128(r, g),
             vt + vbase + (size_t)r * Ssz + chunk*128 + sub*64 + g*8);
    }
    if (tid < 128)
        cp4(st + 32768 + tid*4, mask + (size_t)b * Ssz + chunk*128 + tid);
}

__global__ __launch_bounds__(256, 1) void attn2_k(
    const __half* __restrict__ qb, const __half* __restrict__ kb,
    const __half* __restrict__ vt, const int* __restrict__ mask,
    __half* __restrict__ og)
{
    extern __shared__ char sm_[];
    const uint32_t sbase = smem_u32(sm_);
    const int tid = threadIdx.x, lane = tid & 31, warp = tid >> 5;
    const int q0 = blockIdx.x * 128;
    const int bh = blockIdx.y;
    const int b = bh >> 4, h = bh & 15;

    const size_t qkbase = ((size_t)b * Ssz) * Csz + h * Dh;
    const size_t vbase  = (size_t)bh * Dh * Ssz;

#pragma unroll
    for (int i = 0; i < 4; i++) {
        const int idx = tid + i*256;
        const int r = idx >> 3, g = idx & 7;
        cp16(sbase + tswz128(r, g), qb + qkbase + (size_t)(q0 + r) * Csz + g*8);
    }
    CP_COMMIT();

    const uint32_t kvb = sbase + 16384;
    attn_stage(kb, vt, mask, qkbase, vbase, b, 0, kvb);
    CP_COMMIT();

    float oacc[8][4];
#pragma unroll
    for (int nt = 0; nt < 8; nt++)
#pragma unroll
        for (int c = 0; c < 4; c++) oacc[nt][c] = 0.f;
    float m0 = -1e30f, m1 = -1e30f, l0 = 0.f, l1 = 0.f;
    uint32_t aq[4][4];

    const int cb = (lane & 3) * 2;

    for (int it = 0; it < Ssz/128; it++) {
        if (it + 1 < Ssz/128) {
            attn_stage(kb, vt, mask, qkbase, vbase, b, it+1, kvb + ((it+1)&1)*ATT_STG);
            CP_COMMIT();
            CP_WAIT1();
        } else {
            CP_WAIT0();
        }
        __syncthreads();

        if (it == 0) {
#pragma unroll
            for (int ks = 0; ks < 4; ks++) {
                const int r = warp*16 + (lane & 15);
                const int g = ks*2 + (lane >> 4);
                LDSM4(aq[ks], sbase + tswz128(r, g));
            }
        }

        const uint32_t st = kvb + (it & 1) * ATT_STG;
        const int* Ms = (const int*)(sm_ + 16384 + (it & 1) * ATT_STG + 32768);

        // S = Q K^T : 16 n-tiles of 8 keys
        float sacc[16][4];
#pragma unroll
        for (int nt = 0; nt < 16; nt++)
#pragma unroll
            for (int c = 0; c < 4; c++) sacc[nt][c] = 0.f;

#pragma unroll
        for (int ks = 0; ks < 4; ks++) {
#pragma unroll
            for (int nt = 0; nt < 16; nt++) {
                uint32_t kf[2];
                const int r = nt*8 + (lane & 7);
                const int g = ks*2 + ((lane >> 3) & 1);
                LDSM2(kf, st + tswz128(r, g));
                MMA16816(sacc[nt], aq[ks], kf);
            }
        }

        // scale + mask + online softmax
        float mx0 = -1e30f, mx1 = -1e30f;
#pragma unroll
        for (int nt = 0; nt < 16; nt++) {
            const int c = nt*8 + cb;
            const bool k0m = Ms[c] != 0, k1m = Ms[c+1] != 0;
            sacc[nt][0] = k0m ? sacc[nt][0]*0.125f : -1e30f;
            sacc[nt][1] = k1m ? sacc[nt][1]*0.125f : -1e30f;
            sacc[nt][2] = k0m ? sacc[nt][2]*0.125f : -1e30f;
            sacc[nt][3] = k1m ? sacc[nt][3]*0.125f : -1e30f;
            mx0 = fmaxf(mx0, fmaxf(sacc[nt][0], sacc[nt][1]));
            mx1 = fmaxf(mx1, fmaxf(sacc[nt][2], sacc[nt][3]));
        }
        mx0 = fmaxf(mx0, __shfl_xor_sync(0xffffffffu, mx0, 1));
        mx0 = fmaxf(mx0, __shfl_xor_sync(0xffffffffu, mx0, 2));
        mx1 = fmaxf(mx1, __shfl_xor_sync(0xffffffffu, mx1, 1));
        mx1 = fmaxf(mx1, __shfl_xor_sync(0xffffffffu, mx1, 2));
        const float mn0 = fmaxf(m0, mx0), mn1 = fmaxf(m1, mx1);
        const float c0 = __expf(m0 - mn0), c1 = __expf(m1 - mn1);
        m0 = mn0; m1 = mn1;
        float rs0 = 0.f, rs1 = 0.f;
#pragma unroll
        for (int nt = 0; nt < 16; nt++) {
            sacc[nt][0] = __expf(sacc[nt][0] - mn0);
            sacc[nt][1] = __expf(sacc[nt][1] - mn0);
            sacc[nt][2] = __expf(sacc[nt][2] - mn1);
            sacc[nt][3] = __expf(sacc[nt][3] - mn1);
            rs0 += sacc[nt][0] + sacc[nt][1];
            rs1 += sacc[nt][2] + sacc[nt][3];
        }
        rs0 += __shfl_xor_sync(0xffffffffu, rs0, 1);
        rs0 += __shfl_xor_sync(0xffffffffu, rs0, 2);
        rs1 += __shfl_xor_sync(0xffffffffu, rs1, 1);
        rs1 += __shfl_xor_sync(0xffffffffu, rs1, 2);
        l0 = l0*c0 + rs0;
        l1 = l1*c1 + rs1;
#pragma unroll
        for (int nt = 0; nt < 8; nt++) {
            oacc[nt][0] *= c0; oacc[nt][1] *= c0;
            oacc[nt][2] *= c1; oacc[nt][3] *= c1;
        }

        // O += P V : 8 k-steps of 16 keys; V subtile = ks>>2
#pragma unroll
        for (int ks = 0; ks < 8; ks++) {
            uint32_t pa[4];
            pa[0] = pack_f16(sacc[2*ks][0],   sacc[2*ks][1]);
            pa[1] = pack_f16(sacc[2*ks][2],   sacc[2*ks][3]);
            pa[2] = pack_f16(sacc[2*ks+1][0], sacc[2*ks+1][1]);
            pa[3] = pack_f16(sacc[2*ks+1][2], sacc[2*ks+1][3]);
            const uint32_t vb_off = st + 16384 + (ks >> 2) * 8192;
#pragma unroll
            for (int nt = 0; nt < 8; nt++) {
                uint32_t vf[2];
                const int r = nt*8 + (lane & 7);
                const int g = (ks & 3)*2 + ((lane >> 3) & 1);
                LDSM2(vf, vb_off + tswz128(r, g));
                MMA16816(oacc[nt], pa, vf);
            }
        }
        __syncthreads();
    }

    const float inv0 = 1.f / l0, inv1 = 1.f / l1;
    const int r0 = q0 + warp*16 + (lane >> 2);
#pragma unroll
    for (int nt = 0; nt < 8; nt++) {
        const int c = h*Dh + nt*8 + cb;
        *(__half2*)(og + ((size_t)b*Ssz + r0) * Csz + c) =
            __floats2half2_rn(oacc[nt][0]*inv0, oacc[nt][1]*inv0);
        *(__half2*)(og + ((size_t)b*Ssz + r0 + 8) * Csz + c) =
            __floats2half2_rn(oacc[nt][2]*inv1, oacc[nt][3]*inv1);
    }
}

// ---------------------------------------------------------------------------
extern "C" void kernel_launch(void* const* d_in, const int* in_sizes, int n_in,
                              void* d_out, int out_size)
{
    const float* x    = (const float*)d_in[0];
    const int*   mask = (const int*)  d_in[1];
    const float* W[3]   = {(const float*)d_in[2],  (const float*)d_in[8],  (const float*)d_in[14]};
    const float* Bi[3]  = {(const float*)d_in[3],  (const float*)d_in[9],  (const float*)d_in[15]};
    const float* DW[3]  = {(const float*)d_in[4],  (const float*)d_in[10], (const float*)d_in[16]};
    const float* DWB[3] = {(const float*)d_in[5],  (const float*)d_in[11], (const float*)d_in[17]};
    const float* PW[3]  = {(const float*)d_in[6],  (const float*)d_in[12], (const float*)d_in[18]};
    const float* PWB[3] = {(const float*)d_in[7],  (const float*)d_in[13], (const float*)d_in[19]};
    const float* wo = (const float*)d_in[20];
    const float* bo = (const float*)d_in[21];
    float* out = (float*)d_out;

    __half *ga, *gb, *go, *vb, *gw;
    cudaGetSymbolAddress((void**)&ga, g_a);
    cudaGetSymbolAddress((void**)&gb, g_b);
    cudaGetSymbolAddress((void**)&go, g_o);
    cudaGetSymbolAddress((void**)&vb, g_vb);
    cudaGetSymbolAddress((void**)&gw, g_w);
    const size_t PL = (size_t)Msz * Csz;
    const size_t WL = (size_t)Csz * Csz;

    const int GEMM_SMEM = 2 * G_STG;            // 32768
    const int ATT_SMEM  = 16384 + 2*ATT_STG;    // 82944
    cudaFuncSetAttribute(gemm_f16_k<0,0>, cudaFuncAttributeMaxDynamicSharedMemorySize, GEMM_SMEM);
    cudaFuncSetAttribute(gemm_f16_k<0,1>, cudaFuncAttributeMaxDynamicSharedMemorySize, GEMM_SMEM);
    cudaFuncSetAttribute(gemm_f16_k<1,1>, cudaFuncAttributeMaxDynamicSharedMemorySize, GEMM_SMEM);
    cudaFuncSetAttribute(attn2_k, cudaFuncAttributeMaxDynamicSharedMemorySize, ATT_SMEM);

    const dim3 ggemm1(Csz/128, Msz/128, 1);
    const dim3 ggemm3(Csz/128, Msz/128, 3);
    const dim3 gtr3(Csz/32, Csz/32, 3), btr(32, 8);

    // 1) x -> fp16 (ga0)
    cvt_f16_k<<<(Msz*Csz/4)/256, 256>>>(x, ga);

    // 2) QKV weights -> [N,K] fp16 (batched)
    cvt_trans3_k<<<gtr3, btr>>>(W[0], W[1], W[2], gw, Csz, Csz);

    // 3) batched QKV GEMM: q/k/v = silu(x @ W + b) -> gb[z] (fp16)
    gemm_f16_k<1,1><<<ggemm3, 256, GEMM_SMEM>>>(
        ga, gw, Bi[0], Bi[1], Bi[2], gb,
        Msz, Csz, Csz, 0, WL, PL);

    // 4) depthwise conv fp16->fp16: gb[z] -> ga[z]
    dwconv_f16_k<<<dim3((Msz*Csz/8)/256, 3), 256>>>(
        gb, DW[0], DW[1], DW[2], DWB[0], DWB[1], DWB[2], ga);

    // 5) pointwise weights (already [N,K]) -> fp16 (batched)
    cvt3_k<<<dim3((Csz*Csz/4)/256, 3), 256>>>(PW[0], PW[1], PW[2], gw);

    // 6) batched pointwise GEMM -> gb[z] (fp16)
    gemm_f16_k<0,1><<<ggemm3, 256, GEMM_SMEM>>>(
        ga, gw, PWB[0], PWB[1], PWB[2], gb,
        Msz, Csz, Csz, PL, WL, PL);

    // 7) l2norm q,k (batched), V -> fp16 transposed
    l2norm_f16_k<<<dim3(Msz, 2), 256>>>(gb, ga, PL);
    vtrans_k<<<dim3(Ssz/32, Bsz*Hn*2), btr>>>(gb + 2*PL, vb);

    // 8) out-proj weight -> [N,K] fp16
    cvt_trans3_k<<<dim3(Csz/32, Csz/32, 1), btr>>>(wo, wo, wo, gw, Csz, Csz);

    // 9) attention -> plain fp16 output
    attn2_k<<<dim3(Ssz/128, Bsz*Hn), 256, ATT_SMEM>>>(
        ga, ga + PL, vb, mask, go);

    // 10) out = attn_out @ wo + bo (fp32 out)
    gemm_f16_k<0,0><<<ggemm1, 256, GEMM_SMEM>>>(
        go, gw, bo, bo, bo, out,
        Msz, Csz, Csz, 0, 0, 0);
}